// round 2
// baseline (speedup 1.0000x reference)
#include <cuda_runtime.h>
#include <cstdint>

#define T_STEPS 256
#define BATCH   16
#define EMB     1024
#define HID     1024
#define VOCAB   32000
#define M_TOTAL (T_STEPS * BATCH)   // 4096

// Scratch (static device globals — allocation-free per harness rules)
__device__ float g_U [M_TOTAL * HID];   // U = emb @ W_xh + b_h   (16 MB)
__device__ float g_Hs[M_TOTAL * HID];   // hidden states          (16 MB)
__device__ float g_WT[HID * HID];       // W_hh transposed        (4 MB)

// ---------------------------------------------------------------------------
// K0: transpose W_hh -> g_WT  (g_WT[j][i] = W_hh[i][j])
// ---------------------------------------------------------------------------
__global__ void k_transpose(const float* __restrict__ W) {
    __shared__ float tile[32][33];
    int x = blockIdx.x * 32 + threadIdx.x;
    int y = blockIdx.y * 32 + threadIdx.y;
    #pragma unroll
    for (int i = 0; i < 32; i += 8)
        tile[threadIdx.y + i][threadIdx.x] = W[(size_t)(y + i) * HID + x];
    __syncthreads();
    x = blockIdx.y * 32 + threadIdx.x;
    y = blockIdx.x * 32 + threadIdx.y;
    #pragma unroll
    for (int i = 0; i < 32; i += 8)
        g_WT[(size_t)(y + i) * HID + x] = tile[threadIdx.x][threadIdx.y + i];
}

// ---------------------------------------------------------------------------
// K1: U[m][n] = sum_k W_e[X[m]][k] * W_xh[k][n] + b_h[n]
//     fp32 SIMT tiled GEMM, BM=BN=64, BK=16, 256 threads, 4x4 micro-tile
// ---------------------------------------------------------------------------
__global__ void k_embed_gemm(const int* __restrict__ X,
                             const float* __restrict__ We,
                             const float* __restrict__ Wxh,
                             const float* __restrict__ bh) {
    __shared__ float As[64][17];
    __shared__ float Bs[16][64];
    __shared__ int   sIdx[64];

    const int tid = threadIdx.x;
    const int m0 = blockIdx.y * 64;
    const int n0 = blockIdx.x * 64;

    if (tid < 64) sIdx[tid] = X[m0 + tid];
    __syncthreads();

    const int tx = tid & 15, ty = tid >> 4;
    float acc[4][4];
    #pragma unroll
    for (int i = 0; i < 4; i++)
        #pragma unroll
        for (int j = 0; j < 4; j++) acc[i][j] = 0.f;

    for (int k0 = 0; k0 < EMB; k0 += 16) {
        #pragma unroll
        for (int q = 0; q < 4; q++) {
            int id = tid + q * 256;
            int r = id >> 4, cc = id & 15;
            As[r][cc] = We[(size_t)sIdx[r] * EMB + k0 + cc];
            int rb = id >> 6, cb = id & 63;
            Bs[rb][cb] = Wxh[(size_t)(k0 + rb) * HID + n0 + cb];
        }
        __syncthreads();
        #pragma unroll
        for (int k = 0; k < 16; k++) {
            float ra[4];
            #pragma unroll
            for (int i = 0; i < 4; i++) ra[i] = As[ty * 4 + i][k];
            float4 rbv = *(const float4*)&Bs[k][tx * 4];
            float rb[4] = {rbv.x, rbv.y, rbv.z, rbv.w};
            #pragma unroll
            for (int i = 0; i < 4; i++)
                #pragma unroll
                for (int j = 0; j < 4; j++) acc[i][j] += ra[i] * rb[j];
        }
        __syncthreads();
    }
    #pragma unroll
    for (int i = 0; i < 4; i++)
        #pragma unroll
        for (int j = 0; j < 4; j++)
            g_U[(size_t)(m0 + ty * 4 + i) * HID + n0 + tx * 4 + j] =
                acc[i][j] + bh[n0 + tx * 4 + j];
}

// ---------------------------------------------------------------------------
// K2: one recurrence step: h_t = tanh(U_t + h_{t-1} @ W_hh)
//     grid=64 CTAs x 256 thr; thread owns one (b, j) output; h chunked in smem
// ---------------------------------------------------------------------------
__global__ void k_rnn_step(int t) {
    __shared__ float hs[16][128];
    const int tid = threadIdx.x;
    const int jl = tid & 15, b = tid >> 4;
    const int j = blockIdx.x * 16 + jl;
    const int m = t * BATCH + b;

    float val = g_U[(size_t)m * HID + j];

    if (t > 0) {
        const float* hprev = g_Hs + (size_t)(t - 1) * BATCH * HID;
        const float* wrow  = g_WT + (size_t)j * HID;
        float acc = 0.f;
        for (int ch = 0; ch < 8; ch++) {
            #pragma unroll
            for (int q = 0; q < 2; q++) {
                int lin = tid + q * 256;
                int r = lin >> 5, c = (lin & 31) << 2;
                *(float4*)&hs[r][c] =
                    *(const float4*)&hprev[(size_t)r * HID + ch * 128 + c];
            }
            __syncthreads();
            #pragma unroll
            for (int i = 0; i < 128; i += 4) {
                float4 w  = *(const float4*)&wrow[ch * 128 + i];
                float4 h4 = *(const float4*)&hs[b][i];
                acc += w.x * h4.x + w.y * h4.y + w.z * h4.z + w.w * h4.w;
            }
            __syncthreads();
        }
        val += acc;
    }
    g_Hs[(size_t)m * HID + j] = tanhf(val);
}

// ---------------------------------------------------------------------------
// K3: logits = Hs @ W_hq + b_q   via mma.sync m16n8k8 tf32
//     CTA tile 128x128, BK=32, double-buffered smem, 8 warps of 64x32
// ---------------------------------------------------------------------------
#define AS_STRIDE 36    // 32 + 4 pad (16B aligned rows, conflict-free frags)
#define BS_STRIDE 132   // 128 + 4 pad
#define AS_BUF (128 * AS_STRIDE)
#define BS_BUF (32 * BS_STRIDE)
#define K3_SMEM ((2 * AS_BUF + 2 * BS_BUF) * 4)   // 70656 bytes

__device__ __forceinline__ float ftf32(float x) {
    unsigned u;
    asm("cvt.rna.tf32.f32 %0, %1;" : "=r"(u) : "f"(x));
    return __uint_as_float(u);
}

__device__ __forceinline__ void mma_tf32(float c[4], const unsigned a[4],
                                         const unsigned b[2]) {
    asm volatile(
        "mma.sync.aligned.m16n8k8.row.col.f32.tf32.tf32.f32 "
        "{%0,%1,%2,%3},{%4,%5,%6,%7},{%8,%9},{%0,%1,%2,%3};\n"
        : "+f"(c[0]), "+f"(c[1]), "+f"(c[2]), "+f"(c[3])
        : "r"(a[0]), "r"(a[1]), "r"(a[2]), "r"(a[3]), "r"(b[0]), "r"(b[1]));
}

__device__ __forceinline__ void ldgA(float4* pa, int tid, int m0, int k0) {
    #pragma unroll
    for (int q = 0; q < 4; q++) {
        int id = tid + q * 256;
        int r = id >> 3, c4 = id & 7;
        pa[q] = *(const float4*)&g_Hs[(size_t)(m0 + r) * HID + k0 + c4 * 4];
    }
}
__device__ __forceinline__ void ldgB(float4* pb, int tid, int n0, int k0,
                                     const float* __restrict__ Whq) {
    #pragma unroll
    for (int q = 0; q < 4; q++) {
        int id = tid + q * 256;
        int r = id >> 5, c4 = id & 31;
        pb[q] = *(const float4*)&Whq[(size_t)(k0 + r) * VOCAB + n0 + c4 * 4];
    }
}
__device__ __forceinline__ void stsA(float* Ab, int tid, const float4* pa) {
    #pragma unroll
    for (int q = 0; q < 4; q++) {
        int id = tid + q * 256;
        int r = id >> 3, c4 = id & 7;
        float4 v = pa[q];
        v.x = ftf32(v.x); v.y = ftf32(v.y); v.z = ftf32(v.z); v.w = ftf32(v.w);
        *(float4*)&Ab[r * AS_STRIDE + c4 * 4] = v;
    }
}
__device__ __forceinline__ void stsB(float* Bb, int tid, const float4* pb) {
    #pragma unroll
    for (int q = 0; q < 4; q++) {
        int id = tid + q * 256;
        int r = id >> 5, c4 = id & 31;
        float4 v = pb[q];
        v.x = ftf32(v.x); v.y = ftf32(v.y); v.z = ftf32(v.z); v.w = ftf32(v.w);
        *(float4*)&Bb[r * BS_STRIDE + c4 * 4] = v;
    }
}

__global__ void k_out_gemm(const float* __restrict__ Whq,
                           const float* __restrict__ bq,
                           float* __restrict__ out) {
    extern __shared__ float sm[];
    float* As = sm;                 // 2 buffers of 128 x AS_STRIDE
    float* Bs = sm + 2 * AS_BUF;    // 2 buffers of 32  x BS_STRIDE

    const int tid  = threadIdx.x;
    const int lane = tid & 31, warp = tid >> 5;
    const int gid  = lane >> 2, tig = lane & 3;
    const int wm = (warp >> 2) * 64;   // warp M offset (2 warps along M)
    const int wn = (warp & 3) * 32;    // warp N offset (4 warps along N)
    const int m0 = blockIdx.y * 128;
    const int n0 = blockIdx.x * 128;

    float c[4][4][4];
    #pragma unroll
    for (int mi = 0; mi < 4; mi++)
        #pragma unroll
        for (int ni = 0; ni < 4; ni++)
            #pragma unroll
            for (int r = 0; r < 4; r++) c[mi][ni][r] = 0.f;

    float4 pa[4], pb[4];
    ldgA(pa, tid, m0, 0);
    ldgB(pb, tid, n0, 0, Whq);
    stsA(As, tid, pa);
    stsB(Bs, tid, pb);
    __syncthreads();

    int buf = 0;
    for (int kt = 0; kt < 32; kt++) {
        if (kt < 31) {
            ldgA(pa, tid, m0, (kt + 1) * 32);
            ldgB(pb, tid, n0, (kt + 1) * 32, Whq);
        }
        const float* Ab = As + buf * AS_BUF;
        const float* Bb = Bs + buf * BS_BUF;
        #pragma unroll
        for (int kk = 0; kk < 32; kk += 8) {
            unsigned af[4][4], bf[4][2];
            #pragma unroll
            for (int mi = 0; mi < 4; mi++) {
                int mr = wm + mi * 16 + gid;
                af[mi][0] = __float_as_uint(Ab[mr * AS_STRIDE + kk + tig]);
                af[mi][1] = __float_as_uint(Ab[(mr + 8) * AS_STRIDE + kk + tig]);
                af[mi][2] = __float_as_uint(Ab[mr * AS_STRIDE + kk + tig + 4]);
                af[mi][3] = __float_as_uint(Ab[(mr + 8) * AS_STRIDE + kk + tig + 4]);
            }
            #pragma unroll
            for (int ni = 0; ni < 4; ni++) {
                int nc = wn + ni * 8 + gid;
                bf[ni][0] = __float_as_uint(Bb[(kk + tig) * BS_STRIDE + nc]);
                bf[ni][1] = __float_as_uint(Bb[(kk + tig + 4) * BS_STRIDE + nc]);
            }
            #pragma unroll
            for (int mi = 0; mi < 4; mi++)
                #pragma unroll
                for (int ni = 0; ni < 4; ni++)
                    mma_tf32(c[mi][ni], af[mi], bf[ni]);
        }
        if (kt < 31) {
            stsA(As + (buf ^ 1) * AS_BUF, tid, pa);
            stsB(Bs + (buf ^ 1) * BS_BUF, tid, pb);
        }
        __syncthreads();
        buf ^= 1;
    }

    // Epilogue: add bias, store fp32 logits
    #pragma unroll
    for (int mi = 0; mi < 4; mi++) {
        int mr = m0 + wm + mi * 16 + gid;
        #pragma unroll
        for (int ni = 0; ni < 4; ni++) {
            int nc = n0 + wn + ni * 8 + tig * 2;
            float b0 = bq[nc], b1 = bq[nc + 1];
            float2 v0 = make_float2(c[mi][ni][0] + b0, c[mi][ni][1] + b1);
            float2 v1 = make_float2(c[mi][ni][2] + b0, c[mi][ni][3] + b1);
            *(float2*)&out[(size_t)mr * VOCAB + nc]       = v0;
            *(float2*)&out[(size_t)(mr + 8) * VOCAB + nc] = v1;
        }
    }
}

// ---------------------------------------------------------------------------
extern "C" void kernel_launch(void* const* d_in, const int* in_sizes, int n_in,
                              void* d_out, int out_size) {
    const int*   X   = (const int*)  d_in[0];
    const float* We  = (const float*)d_in[1];
    const float* Wxh = (const float*)d_in[2];
    const float* Whh = (const float*)d_in[3];
    const float* bh  = (const float*)d_in[4];
    const float* Whq = (const float*)d_in[5];
    const float* bq  = (const float*)d_in[6];
    float*       out = (float*)d_out;

    cudaFuncSetAttribute(k_out_gemm,
                         cudaFuncAttributeMaxDynamicSharedMemorySize, K3_SMEM);

    k_transpose<<<dim3(32, 32), dim3(32, 8)>>>(Whh);
    k_embed_gemm<<<dim3(16, 64), 256>>>(X, We, Wxh, bh);
    for (int t = 0; t < T_STEPS; t++)
        k_rnn_step<<<64, 256>>>(t);
    k_out_gemm<<<dim3(VOCAB / 128, M_TOTAL / 128), 256, K3_SMEM>>>(Whq, bq, out);
}

// round 3
// speedup vs baseline: 3.1447x; 3.1447x over previous
#include <cuda_runtime.h>
#include <cstdint>

#define T_STEPS 256
#define BATCH   16
#define EMB     1024
#define HID     1024
#define VOCAB   32000
#define M_TOTAL (T_STEPS * BATCH)   // 4096

// Scratch (static device globals — allocation-free per harness rules)
__device__ float    g_U [M_TOTAL * HID];   // U = emb @ W_xh + b_h   (16 MB)
__device__ float    g_Hs[M_TOTAL * HID];   // hidden states          (16 MB)
__device__ unsigned g_gen;                 // grid-barrier counter (memset/launch)

// ---------------------------------------------------------------------------
// K1: U[m][n] = sum_k W_e[X[m]][k] * W_xh[k][n] + b_h[n]
// ---------------------------------------------------------------------------
__global__ void k_embed_gemm(const int* __restrict__ X,
                             const float* __restrict__ We,
                             const float* __restrict__ Wxh,
                             const float* __restrict__ bh) {
    __shared__ float As[64][17];
    __shared__ float Bs[16][64];
    __shared__ int   sIdx[64];

    const int tid = threadIdx.x;
    const int m0 = blockIdx.y * 64;
    const int n0 = blockIdx.x * 64;

    if (tid < 64) sIdx[tid] = X[m0 + tid];
    __syncthreads();

    const int tx = tid & 15, ty = tid >> 4;
    float acc[4][4];
    #pragma unroll
    for (int i = 0; i < 4; i++)
        #pragma unroll
        for (int j = 0; j < 4; j++) acc[i][j] = 0.f;

    for (int k0 = 0; k0 < EMB; k0 += 16) {
        #pragma unroll
        for (int q = 0; q < 4; q++) {
            int id = tid + q * 256;
            int r = id >> 4, cc = id & 15;
            As[r][cc] = We[(size_t)sIdx[r] * EMB + k0 + cc];
            int rb = id >> 6, cb = id & 63;
            Bs[rb][cb] = Wxh[(size_t)(k0 + rb) * HID + n0 + cb];
        }
        __syncthreads();
        #pragma unroll
        for (int k = 0; k < 16; k++) {
            float ra[4];
            #pragma unroll
            for (int i = 0; i < 4; i++) ra[i] = As[ty * 4 + i][k];
            float4 rbv = *(const float4*)&Bs[k][tx * 4];
            float rb[4] = {rbv.x, rbv.y, rbv.z, rbv.w};
            #pragma unroll
            for (int i = 0; i < 4; i++)
                #pragma unroll
                for (int j = 0; j < 4; j++) acc[i][j] += ra[i] * rb[j];
        }
        __syncthreads();
    }
    #pragma unroll
    for (int i = 0; i < 4; i++)
        #pragma unroll
        for (int j = 0; j < 4; j++)
            g_U[(size_t)(m0 + ty * 4 + i) * HID + n0 + tx * 4 + j] =
                acc[i][j] + bh[n0 + tx * 4 + j];
}

// ---------------------------------------------------------------------------
// K2 (persistent): all 256 recurrence steps in ONE launch.
//   128 CTAs x 256 threads. CTA c owns output columns j in [c*8, c*8+8).
//   W_hh^T slice (8 x 1024) lives in smem for the whole kernel.
//   Per step: stream h_{t-1} (16x1024) in 4 double-buffered chunks of 256,
//   each thread = (b, jl, k-half), 512 MACs; smem reduce pairs; tanh; store;
//   device-wide generation barrier (single atomic counter, 128 CTAs resident).
// ---------------------------------------------------------------------------
#define NCTA 128
#define JPC  8              // j columns per CTA
#define WS   1028           // Wsm row stride (floats): 1028 % 32 == 4 -> conflict-free
#define HS   260            // hs row stride (floats):  260 % 32 == 4 -> conflict-free
#define CHUNK 256           // k per chunk
#define RNN_SMEM ((JPC * WS + 2 * BATCH * HS + 256) * 4)

__global__ void __launch_bounds__(256, 1) k_rnn(const float* __restrict__ Whh) {
    extern __shared__ float sm[];
    float* Wsm = sm;                       // [JPC][WS]
    float* hsm = sm + JPC * WS;            // [2][BATCH][HS]
    float* red = hsm + 2 * BATCH * HS;     // [256]

    const int tid  = threadIdx.x;
    const int pair = tid & 127;
    const int jl   = pair & 7;             // j within CTA
    const int b    = pair >> 3;            // batch index
    const int half = tid >> 7;             // k-half (0/1)
    const int j0   = blockIdx.x * JPC;
    const int koff = half * 128;           // k offset within a chunk

    // One-time: load W_hh^T slice: Wsm[jl][k] = Whh[k][j0+jl]
    for (int idx = tid; idx < JPC * HID; idx += 256) {
        int k = idx >> 3, jj = idx & 7;
        Wsm[jj * WS + k] = Whh[(size_t)k * HID + j0 + jj];
    }
    __syncthreads();

    const int ld_row = (tid + 0) >> 6;          // 0..15 (b row for h loads)
    // each thread loads 4 float4 per chunk: f4 index = tid + q*256
    for (int t = 0; t < T_STEPS; t++) {
        float hsum = 0.f;

        if (t > 0) {
            const float* hp = g_Hs + (size_t)(t - 1) * BATCH * HID;
            float4 acc = make_float4(0.f, 0.f, 0.f, 0.f);
            float4 r[4];

            // prefetch chunk 0
            #pragma unroll
            for (int q = 0; q < 4; q++) {
                int f4 = tid + q * 256;
                int row = f4 >> 6, c4 = f4 & 63;
                r[q] = __ldcg((const float4*)&hp[(size_t)row * HID + c4 * 4]);
            }
            #pragma unroll
            for (int q = 0; q < 4; q++) {
                int f4 = tid + q * 256;
                int row = f4 >> 6, c4 = f4 & 63;
                *(float4*)&hsm[row * HS + c4 * 4] = r[q];
            }
            __syncthreads();

            #pragma unroll
            for (int ch = 0; ch < 4; ch++) {
                if (ch < 3) {
                    #pragma unroll
                    for (int q = 0; q < 4; q++) {
                        int f4 = tid + q * 256;
                        int row = f4 >> 6, c4 = f4 & 63;
                        r[q] = __ldcg((const float4*)
                            &hp[(size_t)row * HID + (ch + 1) * CHUNK + c4 * 4]);
                    }
                }
                const float* wrow = Wsm + jl * WS + ch * CHUNK + koff;
                const float* hrow = hsm + (ch & 1) * BATCH * HS + b * HS + koff;
                #pragma unroll
                for (int kk = 0; kk < 128; kk += 4) {
                    float4 w4 = *(const float4*)&wrow[kk];
                    float4 h4 = *(const float4*)&hrow[kk];
                    acc.x += w4.x * h4.x;
                    acc.y += w4.y * h4.y;
                    acc.z += w4.z * h4.z;
                    acc.w += w4.w * h4.w;
                }
                if (ch < 3) {
                    float* dst = hsm + ((ch + 1) & 1) * BATCH * HS;
                    #pragma unroll
                    for (int q = 0; q < 4; q++) {
                        int f4 = tid + q * 256;
                        int row = f4 >> 6, c4 = f4 & 63;
                        *(float4*)&dst[row * HS + c4 * 4] = r[q];
                    }
                }
                __syncthreads();
            }
            hsum = (acc.x + acc.y) + (acc.z + acc.w);
        }

        // reduce the two k-halves, add U, tanh, store h_t
        red[tid] = hsum;
        __syncthreads();
        if (tid < 128) {
            const size_t m = (size_t)t * BATCH + b;
            float val = g_U[m * HID + j0 + jl] + red[tid] + red[tid + 128];
            g_Hs[m * HID + j0 + jl] = tanhf(val);
        }
        __threadfence();
        __syncthreads();

        // device-wide barrier (skip after last step)
        if (t < T_STEPS - 1) {
            if (tid == 0) {
                atomicAdd(&g_gen, 1u);
                const unsigned target = (unsigned)NCTA * (t + 1);
                while (*(volatile unsigned*)&g_gen < target) __nanosleep(64);
                __threadfence();
            }
            __syncthreads();
        }
    }
}

// ---------------------------------------------------------------------------
// K3: logits = Hs @ W_hq + b_q   via mma.sync m16n8k8 tf32
// ---------------------------------------------------------------------------
#define AS_STRIDE 36
#define BS_STRIDE 132
#define AS_BUF (128 * AS_STRIDE)
#define BS_BUF (32 * BS_STRIDE)
#define K3_SMEM ((2 * AS_BUF + 2 * BS_BUF) * 4)   // 70656 bytes

__device__ __forceinline__ float ftf32(float x) {
    unsigned u;
    asm("cvt.rna.tf32.f32 %0, %1;" : "=r"(u) : "f"(x));
    return __uint_as_float(u);
}

__device__ __forceinline__ void mma_tf32(float c[4], const unsigned a[4],
                                         const unsigned b[2]) {
    asm volatile(
        "mma.sync.aligned.m16n8k8.row.col.f32.tf32.tf32.f32 "
        "{%0,%1,%2,%3},{%4,%5,%6,%7},{%8,%9},{%0,%1,%2,%3};\n"
        : "+f"(c[0]), "+f"(c[1]), "+f"(c[2]), "+f"(c[3])
        : "r"(a[0]), "r"(a[1]), "r"(a[2]), "r"(a[3]), "r"(b[0]), "r"(b[1]));
}

__device__ __forceinline__ void ldgA(float4* pa, int tid, int m0, int k0) {
    #pragma unroll
    for (int q = 0; q < 4; q++) {
        int id = tid + q * 256;
        int r = id >> 3, c4 = id & 7;
        pa[q] = *(const float4*)&g_Hs[(size_t)(m0 + r) * HID + k0 + c4 * 4];
    }
}
__device__ __forceinline__ void ldgB(float4* pb, int tid, int n0, int k0,
                                     const float* __restrict__ Whq) {
    #pragma unroll
    for (int q = 0; q < 4; q++) {
        int id = tid + q * 256;
        int r = id >> 5, c4 = id & 31;
        pb[q] = *(const float4*)&Whq[(size_t)(k0 + r) * VOCAB + n0 + c4 * 4];
    }
}
__device__ __forceinline__ void stsA(float* Ab, int tid, const float4* pa) {
    #pragma unroll
    for (int q = 0; q < 4; q++) {
        int id = tid + q * 256;
        int r = id >> 3, c4 = id & 7;
        float4 v = pa[q];
        v.x = ftf32(v.x); v.y = ftf32(v.y); v.z = ftf32(v.z); v.w = ftf32(v.w);
        *(float4*)&Ab[r * AS_STRIDE + c4 * 4] = v;
    }
}
__device__ __forceinline__ void stsB(float* Bb, int tid, const float4* pb) {
    #pragma unroll
    for (int q = 0; q < 4; q++) {
        int id = tid + q * 256;
        int r = id >> 5, c4 = id & 31;
        float4 v = pb[q];
        v.x = ftf32(v.x); v.y = ftf32(v.y); v.z = ftf32(v.z); v.w = ftf32(v.w);
        *(float4*)&Bb[r * BS_STRIDE + c4 * 4] = v;
    }
}

__global__ void k_out_gemm(const float* __restrict__ Whq,
                           const float* __restrict__ bq,
                           float* __restrict__ out) {
    extern __shared__ float sm[];
    float* As = sm;
    float* Bs = sm + 2 * AS_BUF;

    const int tid  = threadIdx.x;
    const int lane = tid & 31, warp = tid >> 5;
    const int gid  = lane >> 2, tig = lane & 3;
    const int wm = (warp >> 2) * 64;
    const int wn = (warp & 3) * 32;
    const int m0 = blockIdx.y * 128;
    const int n0 = blockIdx.x * 128;

    float c[4][4][4];
    #pragma unroll
    for (int mi = 0; mi < 4; mi++)
        #pragma unroll
        for (int ni = 0; ni < 4; ni++)
            #pragma unroll
            for (int r = 0; r < 4; r++) c[mi][ni][r] = 0.f;

    float4 pa[4], pb[4];
    ldgA(pa, tid, m0, 0);
    ldgB(pb, tid, n0, 0, Whq);
    stsA(As, tid, pa);
    stsB(Bs, tid, pb);
    __syncthreads();

    int buf = 0;
    for (int kt = 0; kt < 32; kt++) {
        if (kt < 31) {
            ldgA(pa, tid, m0, (kt + 1) * 32);
            ldgB(pb, tid, n0, (kt + 1) * 32, Whq);
        }
        const float* Ab = As + buf * AS_BUF;
        const float* Bb = Bs + buf * BS_BUF;
        #pragma unroll
        for (int kk = 0; kk < 32; kk += 8) {
            unsigned af[4][4], bf[4][2];
            #pragma unroll
            for (int mi = 0; mi < 4; mi++) {
                int mr = wm + mi * 16 + gid;
                af[mi][0] = __float_as_uint(Ab[mr * AS_STRIDE + kk + tig]);
                af[mi][1] = __float_as_uint(Ab[(mr + 8) * AS_STRIDE + kk + tig]);
                af[mi][2] = __float_as_uint(Ab[mr * AS_STRIDE + kk + tig + 4]);
                af[mi][3] = __float_as_uint(Ab[(mr + 8) * AS_STRIDE + kk + tig + 4]);
            }
            #pragma unroll
            for (int ni = 0; ni < 4; ni++) {
                int nc = wn + ni * 8 + gid;
                bf[ni][0] = __float_as_uint(Bb[(kk + tig) * BS_STRIDE + nc]);
                bf[ni][1] = __float_as_uint(Bb[(kk + tig + 4) * BS_STRIDE + nc]);
            }
            #pragma unroll
            for (int mi = 0; mi < 4; mi++)
                #pragma unroll
                for (int ni = 0; ni < 4; ni++)
                    mma_tf32(c[mi][ni], af[mi], bf[ni]);
        }
        if (kt < 31) {
            stsA(As + (buf ^ 1) * AS_BUF, tid, pa);
            stsB(Bs + (buf ^ 1) * BS_BUF, tid, pb);
        }
        __syncthreads();
        buf ^= 1;
    }

    #pragma unroll
    for (int mi = 0; mi < 4; mi++) {
        int mr = m0 + wm + mi * 16 + gid;
        #pragma unroll
        for (int ni = 0; ni < 4; ni++) {
            int nc = n0 + wn + ni * 8 + tig * 2;
            float b0 = bq[nc], b1 = bq[nc + 1];
            float2 v0 = make_float2(c[mi][ni][0] + b0, c[mi][ni][1] + b1);
            float2 v1 = make_float2(c[mi][ni][2] + b0, c[mi][ni][3] + b1);
            *(float2*)&out[(size_t)mr * VOCAB + nc]       = v0;
            *(float2*)&out[(size_t)(mr + 8) * VOCAB + nc] = v1;
        }
    }
}

// ---------------------------------------------------------------------------
extern "C" void kernel_launch(void* const* d_in, const int* in_sizes, int n_in,
                              void* d_out, int out_size) {
    const int*   X   = (const int*)  d_in[0];
    const float* We  = (const float*)d_in[1];
    const float* Wxh = (const float*)d_in[2];
    const float* Whh = (const float*)d_in[3];
    const float* bh  = (const float*)d_in[4];
    const float* Whq = (const float*)d_in[5];
    const float* bq  = (const float*)d_in[6];
    float*       out = (float*)d_out;

    cudaFuncSetAttribute(k_out_gemm,
                         cudaFuncAttributeMaxDynamicSharedMemorySize, K3_SMEM);
    cudaFuncSetAttribute(k_rnn,
                         cudaFuncAttributeMaxDynamicSharedMemorySize, RNN_SMEM);

    // reset the device-wide barrier counter (graph-capturable memset node)
    void* gen_ptr = nullptr;
    cudaGetSymbolAddress(&gen_ptr, g_gen);
    cudaMemsetAsync(gen_ptr, 0, sizeof(unsigned), 0);

    k_embed_gemm<<<dim3(16, 64), 256>>>(X, We, Wxh, bh);
    k_rnn<<<NCTA, 256, RNN_SMEM>>>(Whh);
    k_out_gemm<<<dim3(VOCAB / 128, M_TOTAL / 128), 256, K3_SMEM>>>(Whq, bq, out);
}

// round 6
// speedup vs baseline: 3.6055x; 1.1465x over previous
#include <cuda_runtime.h>
#include <cstdint>

#define T_STEPS 256
#define BATCH   16
#define EMB     1024
#define HID     1024
#define VOCAB   32000
#define M_TOTAL (T_STEPS * BATCH)   // 4096

// Scratch (static device globals — allocation-free per harness rules)
__device__ float    g_U    [M_TOTAL * HID];   // 16 MB
__device__ float    g_Hs   [M_TOTAL * HID];   // 16 MB (fp32 hidden states)
__device__ float    g_Hs32 [M_TOTAL * HID];   // 16 MB (tf32-rounded copy)
__device__ float    g_Whq32[HID * VOCAB];     // 128 MB (tf32-rounded W_hq)
__device__ unsigned g_gen;                    // grid-barrier counter

// ===========================================================================
// helpers
// ===========================================================================
__device__ __forceinline__ float ftf32(float x) {
    unsigned u;
    asm("cvt.rna.tf32.f32 %0, %1;" : "=r"(u) : "f"(x));
    return __uint_as_float(u);
}
__device__ __forceinline__ uint32_t smem_u32(const void* p) {
    uint32_t a;
    asm("{ .reg .u64 t; cvta.to.shared.u64 t, %1; cvt.u32.u64 %0, t; }"
        : "=r"(a) : "l"(p));
    return a;
}
__device__ __forceinline__ void cp16(uint32_t dst, const void* src) {
    asm volatile("cp.async.cg.shared.global [%0], [%1], 16;"
                 :: "r"(dst), "l"(src) : "memory");
}
#define CP_COMMIT() asm volatile("cp.async.commit_group;" ::: "memory")
#define CP_WAIT2()  asm volatile("cp.async.wait_group 2;" ::: "memory")
#define CP_WAIT0()  asm volatile("cp.async.wait_group 0;" ::: "memory")

__device__ __forceinline__ void mma_tf32(float c[4], const unsigned a[4],
                                         const unsigned b[2]) {
    asm volatile(
        "mma.sync.aligned.m16n8k8.row.col.f32.tf32.tf32.f32 "
        "{%0,%1,%2,%3},{%4,%5,%6,%7},{%8,%9},{%0,%1,%2,%3};\n"
        : "+f"(c[0]), "+f"(c[1]), "+f"(c[2]), "+f"(c[3])
        : "r"(a[0]), "r"(a[1]), "r"(a[2]), "r"(a[3]), "r"(b[0]), "r"(b[1]));
}

// ===========================================================================
// K_round: elementwise tf32-rne rounding (float4 strided)
// ===========================================================================
__global__ void k_round(const float* __restrict__ src, float* __restrict__ dst,
                        int n4) {
    int i = blockIdx.x * blockDim.x + threadIdx.x;
    if (i < n4) {
        float4 v = ((const float4*)src)[i];
        v.x = ftf32(v.x); v.y = ftf32(v.y); v.z = ftf32(v.z); v.w = ftf32(v.w);
        ((float4*)dst)[i] = v;
    }
}

// ===========================================================================
// K1: U = gather(W_e, X) @ W_xh + b_h  via legacy mma.sync tf32
//     BM=BN=128, BK=32, 256 thr, 8 warps of 64x32
// ===========================================================================
#define AS_STRIDE 36
#define BS_STRIDE 132
#define AS_BUF (128 * AS_STRIDE)
#define BS_BUF (32 * BS_STRIDE)
#define K1_SMEM ((2 * AS_BUF + 2 * BS_BUF) * 4 + 512)

__global__ void k_embed_mma(const int* __restrict__ X,
                            const float* __restrict__ We,
                            const float* __restrict__ Wxh,
                            const float* __restrict__ bh) {
    extern __shared__ float sm[];
    float* As = sm;
    float* Bs = sm + 2 * AS_BUF;
    int*   sIdx = (int*)(sm + 2 * AS_BUF + 2 * BS_BUF);

    const int tid  = threadIdx.x;
    const int lane = tid & 31, warp = tid >> 5;
    const int gid  = lane >> 2, tig = lane & 3;
    const int wm = (warp >> 2) * 64;
    const int wn = (warp & 3) * 32;
    const int m0 = blockIdx.y * 128;
    const int n0 = blockIdx.x * 128;

    if (tid < 128) sIdx[tid] = X[m0 + tid];
    __syncthreads();

    float c[4][4][4];
    #pragma unroll
    for (int mi = 0; mi < 4; mi++)
        #pragma unroll
        for (int ni = 0; ni < 4; ni++)
            #pragma unroll
            for (int r = 0; r < 4; r++) c[mi][ni][r] = 0.f;

    float4 pa[4], pb[4];
    auto ldA = [&](int k0) {
        #pragma unroll
        for (int q = 0; q < 4; q++) {
            int id = tid + q * 256, r = id >> 3, c4 = id & 7;
            pa[q] = *(const float4*)&We[(size_t)sIdx[r] * EMB + k0 + c4 * 4];
        }
    };
    auto ldB = [&](int k0) {
        #pragma unroll
        for (int q = 0; q < 4; q++) {
            int id = tid + q * 256, r = id >> 5, c4 = id & 31;
            pb[q] = *(const float4*)&Wxh[(size_t)(k0 + r) * HID + n0 + c4 * 4];
        }
    };
    auto stA = [&](float* Ab) {
        #pragma unroll
        for (int q = 0; q < 4; q++) {
            int id = tid + q * 256, r = id >> 3, c4 = id & 7;
            float4 v = pa[q];
            v.x = ftf32(v.x); v.y = ftf32(v.y); v.z = ftf32(v.z); v.w = ftf32(v.w);
            *(float4*)&Ab[r * AS_STRIDE + c4 * 4] = v;
        }
    };
    auto stB = [&](float* Bb) {
        #pragma unroll
        for (int q = 0; q < 4; q++) {
            int id = tid + q * 256, r = id >> 5, c4 = id & 31;
            float4 v = pb[q];
            v.x = ftf32(v.x); v.y = ftf32(v.y); v.z = ftf32(v.z); v.w = ftf32(v.w);
            *(float4*)&Bb[r * BS_STRIDE + c4 * 4] = v;
        }
    };

    ldA(0); ldB(0);
    stA(As); stB(Bs);
    __syncthreads();

    int buf = 0;
    for (int kt = 0; kt < 32; kt++) {
        if (kt < 31) { ldA((kt + 1) * 32); ldB((kt + 1) * 32); }
        const float* Ab = As + buf * AS_BUF;
        const float* Bb = Bs + buf * BS_BUF;
        #pragma unroll
        for (int kk = 0; kk < 32; kk += 8) {
            unsigned af[4][4], bf[4][2];
            #pragma unroll
            for (int mi = 0; mi < 4; mi++) {
                int mr = wm + mi * 16 + gid;
                af[mi][0] = __float_as_uint(Ab[mr * AS_STRIDE + kk + tig]);
                af[mi][1] = __float_as_uint(Ab[(mr + 8) * AS_STRIDE + kk + tig]);
                af[mi][2] = __float_as_uint(Ab[mr * AS_STRIDE + kk + tig + 4]);
                af[mi][3] = __float_as_uint(Ab[(mr + 8) * AS_STRIDE + kk + tig + 4]);
            }
            #pragma unroll
            for (int ni = 0; ni < 4; ni++) {
                int nc = wn + ni * 8 + gid;
                bf[ni][0] = __float_as_uint(Bb[(kk + tig) * BS_STRIDE + nc]);
                bf[ni][1] = __float_as_uint(Bb[(kk + tig + 4) * BS_STRIDE + nc]);
            }
            #pragma unroll
            for (int mi = 0; mi < 4; mi++)
                #pragma unroll
                for (int ni = 0; ni < 4; ni++)
                    mma_tf32(c[mi][ni], af[mi], bf[ni]);
        }
        if (kt < 31) { stA(As + (buf ^ 1) * AS_BUF); stB(Bs + (buf ^ 1) * BS_BUF); }
        __syncthreads();
        buf ^= 1;
    }

    #pragma unroll
    for (int mi = 0; mi < 4; mi++) {
        int mr = m0 + wm + mi * 16 + gid;
        #pragma unroll
        for (int ni = 0; ni < 4; ni++) {
            int nc = n0 + wn + ni * 8 + tig * 2;
            float b0 = bh[nc], b1 = bh[nc + 1];
            float2 v0 = make_float2(c[mi][ni][0] + b0, c[mi][ni][1] + b1);
            float2 v1 = make_float2(c[mi][ni][2] + b0, c[mi][ni][3] + b1);
            *(float2*)&g_U[(size_t)mr * HID + nc]       = v0;
            *(float2*)&g_U[(size_t)(mr + 8) * HID + nc] = v1;
        }
    }
}

// ===========================================================================
// K2 (persistent): 256 recurrence steps, one launch (unchanged, known-good)
// ===========================================================================
#define NCTA 128
#define JPC  8
#define WS   1028
#define HS   260
#define CHUNK 256
#define RNN_SMEM ((JPC * WS + 2 * BATCH * HS + 256) * 4)

__global__ void __launch_bounds__(256, 1) k_rnn(const float* __restrict__ Whh) {
    extern __shared__ float sm[];
    float* Wsm = sm;
    float* hsm = sm + JPC * WS;
    float* red = hsm + 2 * BATCH * HS;

    const int tid  = threadIdx.x;
    const int pair = tid & 127;
    const int jl   = pair & 7;
    const int b    = pair >> 3;
    const int half = tid >> 7;
    const int j0   = blockIdx.x * JPC;
    const int koff = half * 128;

    for (int idx = tid; idx < JPC * HID; idx += 256) {
        int k = idx >> 3, jj = idx & 7;
        Wsm[jj * WS + k] = Whh[(size_t)k * HID + j0 + jj];
    }
    __syncthreads();

    for (int t = 0; t < T_STEPS; t++) {
        float hsum = 0.f;
        if (t > 0) {
            const float* hp = g_Hs + (size_t)(t - 1) * BATCH * HID;
            float4 acc = make_float4(0.f, 0.f, 0.f, 0.f);
            float4 r[4];
            #pragma unroll
            for (int q = 0; q < 4; q++) {
                int f4 = tid + q * 256, row = f4 >> 6, c4 = f4 & 63;
                r[q] = __ldcg((const float4*)&hp[(size_t)row * HID + c4 * 4]);
            }
            #pragma unroll
            for (int q = 0; q < 4; q++) {
                int f4 = tid + q * 256, row = f4 >> 6, c4 = f4 & 63;
                *(float4*)&hsm[row * HS + c4 * 4] = r[q];
            }
            __syncthreads();
            #pragma unroll
            for (int ch = 0; ch < 4; ch++) {
                if (ch < 3) {
                    #pragma unroll
                    for (int q = 0; q < 4; q++) {
                        int f4 = tid + q * 256, row = f4 >> 6, c4 = f4 & 63;
                        r[q] = __ldcg((const float4*)
                            &hp[(size_t)row * HID + (ch + 1) * CHUNK + c4 * 4]);
                    }
                }
                const float* wrow = Wsm + jl * WS + ch * CHUNK + koff;
                const float* hrow = hsm + (ch & 1) * BATCH * HS + b * HS + koff;
                #pragma unroll
                for (int kk = 0; kk < 128; kk += 4) {
                    float4 w4 = *(const float4*)&wrow[kk];
                    float4 h4 = *(const float4*)&hrow[kk];
                    acc.x += w4.x * h4.x;
                    acc.y += w4.y * h4.y;
                    acc.z += w4.z * h4.z;
                    acc.w += w4.w * h4.w;
                }
                if (ch < 3) {
                    float* dst = hsm + ((ch + 1) & 1) * BATCH * HS;
                    #pragma unroll
                    for (int q = 0; q < 4; q++) {
                        int f4 = tid + q * 256, row = f4 >> 6, c4 = f4 & 63;
                        *(float4*)&dst[row * HS + c4 * 4] = r[q];
                    }
                }
                __syncthreads();
            }
            hsum = (acc.x + acc.y) + (acc.z + acc.w);
        }

        red[tid] = hsum;
        __syncthreads();
        if (tid < 128) {
            const size_t m = (size_t)t * BATCH + b;
            float val = g_U[m * HID + j0 + jl] + red[tid] + red[tid + 128];
            g_Hs[m * HID + j0 + jl] = tanhf(val);
        }
        __threadfence();
        __syncthreads();

        if (t < T_STEPS - 1) {
            if (tid == 0) {
                atomicAdd(&g_gen, 1u);
                const unsigned target = (unsigned)NCTA * (t + 1);
                while (*(volatile unsigned*)&g_gen < target) __nanosleep(64);
                __threadfence();
            }
            __syncthreads();
        }
    }
}

// ===========================================================================
// K3: logits = Hs32 @ Whq32 + b_q   (legacy mma tf32, cp.async 4-stage)
//     CTA 128x256, BK=16, 256 thr, 8 warps of 64x64
//     A smem [m][k] stride 20, B smem [k][n] stride 264 (both conflict-free)
// ===========================================================================
#define BM3 128
#define BN3 256
#define BK3 16
#define A3S 20                              // A row stride (floats)
#define B3S 264                             // B row stride (floats)
#define A3_BYTES (BM3 * A3S * 4)            // 10240
#define B3_BYTES (BK3 * B3S * 4)            // 16896
#define STG3 (A3_BYTES + B3_BYTES)          // 27136
#define K3_SMEM (4 * STG3)                  // 108544

__global__ void __launch_bounds__(256, 1)
k_out_gemm2(const float* __restrict__ bq, float* __restrict__ out) {
    extern __shared__ char smc[];
    const uint32_t sb = smem_u32(smc);

    const int tid  = threadIdx.x;
    const int lane = tid & 31, warp = tid >> 5;
    const int gid  = lane >> 2, tig = lane & 3;
    const int wm = (warp & 1) * 64;       // 2 warps along M
    const int wn = (warp >> 1) * 64;      // 4 warps along N
    const int m0 = blockIdx.x * BM3;      // m fastest -> B tile L2 reuse
    const int n0 = blockIdx.y * BN3;

    auto issue = [&](int kt) {
        const int s = kt & 3;
        const uint32_t ab = sb + s * STG3;
        const uint32_t bb = ab + A3_BYTES;
        const int k0 = kt * BK3;
        #pragma unroll
        for (int q = 0; q < 2; q++) {                 // A: 512 16B chunks
            int id = tid + q * 256;
            int m = id >> 2, kq = id & 3;
            cp16(ab + m * (A3S * 4) + kq * 16,
                 &g_Hs32[(size_t)(m0 + m) * HID + k0 + kq * 4]);
        }
        #pragma unroll
        for (int q = 0; q < 4; q++) {                 // B: 1024 16B chunks
            int id = tid + q * 256;
            int k = id >> 6, n4 = id & 63;
            cp16(bb + k * (B3S * 4) + n4 * 16,
                 &g_Whq32[(size_t)(k0 + k) * VOCAB + n0 + n4 * 4]);
        }
        CP_COMMIT();
    };

    float c[4][8][4];
    #pragma unroll
    for (int mi = 0; mi < 4; mi++)
        #pragma unroll
        for (int ni = 0; ni < 8; ni++)
            #pragma unroll
            for (int r = 0; r < 4; r++) c[mi][ni][r] = 0.f;

    issue(0); issue(1); issue(2);

    for (int kt = 0; kt < 64; kt++) {
        CP_WAIT2();
        __syncthreads();
        if (kt + 3 < 64) issue(kt + 3);

        const int s = kt & 3;
        const float* As = (const float*)(smc + s * STG3);
        const float* Bs = (const float*)(smc + s * STG3 + A3_BYTES);

        #pragma unroll
        for (int kk = 0; kk < BK3; kk += 8) {
            unsigned af[4][4], bf[8][2];
            #pragma unroll
            for (int mi = 0; mi < 4; mi++) {
                int mr = wm + mi * 16 + gid;
                af[mi][0] = __float_as_uint(As[mr * A3S + kk + tig]);
                af[mi][1] = __float_as_uint(As[(mr + 8) * A3S + kk + tig]);
                af[mi][2] = __float_as_uint(As[mr * A3S + kk + tig + 4]);
                af[mi][3] = __float_as_uint(As[(mr + 8) * A3S + kk + tig + 4]);
            }
            #pragma unroll
            for (int ni = 0; ni < 8; ni++) {
                int nc = wn + ni * 8 + gid;
                bf[ni][0] = __float_as_uint(Bs[(kk + tig) * B3S + nc]);
                bf[ni][1] = __float_as_uint(Bs[(kk + tig + 4) * B3S + nc]);
            }
            #pragma unroll
            for (int mi = 0; mi < 4; mi++)
                #pragma unroll
                for (int ni = 0; ni < 8; ni++)
                    mma_tf32(c[mi][ni], af[mi], bf[ni]);
        }
        __syncthreads();
    }
    CP_WAIT0();

    // Epilogue: +bias, fp32 float2 stores
    #pragma unroll
    for (int mi = 0; mi < 4; mi++) {
        int mr = m0 + wm + mi * 16 + gid;
        #pragma unroll
        for (int ni = 0; ni < 8; ni++) {
            int nc = n0 + wn + ni * 8 + tig * 2;
            float b0 = bq[nc], b1 = bq[nc + 1];
            float2 v0 = make_float2(c[mi][ni][0] + b0, c[mi][ni][1] + b1);
            float2 v1 = make_float2(c[mi][ni][2] + b0, c[mi][ni][3] + b1);
            *(float2*)&out[(size_t)mr * VOCAB + nc]       = v0;
            *(float2*)&out[(size_t)(mr + 8) * VOCAB + nc] = v1;
        }
    }
}

// ===========================================================================
extern "C" void kernel_launch(void* const* d_in, const int* in_sizes, int n_in,
                              void* d_out, int out_size) {
    const int*   X   = (const int*)  d_in[0];
    const float* We  = (const float*)d_in[1];
    const float* Wxh = (const float*)d_in[2];
    const float* Whh = (const float*)d_in[3];
    const float* bh  = (const float*)d_in[4];
    const float* Whq = (const float*)d_in[5];
    const float* bq  = (const float*)d_in[6];
    float*       out = (float*)d_out;

    cudaFuncSetAttribute(k_embed_mma,
                         cudaFuncAttributeMaxDynamicSharedMemorySize, K1_SMEM);
    cudaFuncSetAttribute(k_rnn,
                         cudaFuncAttributeMaxDynamicSharedMemorySize, RNN_SMEM);
    cudaFuncSetAttribute(k_out_gemm2,
                         cudaFuncAttributeMaxDynamicSharedMemorySize, K3_SMEM);

    void *gen_ptr = nullptr, *whq32 = nullptr, *hs = nullptr, *hs32 = nullptr;
    cudaGetSymbolAddress(&gen_ptr, g_gen);
    cudaGetSymbolAddress(&whq32, g_Whq32);
    cudaGetSymbolAddress(&hs,    g_Hs);
    cudaGetSymbolAddress(&hs32,  g_Hs32);

    cudaMemsetAsync(gen_ptr, 0, sizeof(unsigned), 0);

    // Pre-round W_hq to tf32 (rne) once
    k_round<<<(HID * VOCAB / 4 + 255) / 256, 256>>>(Whq, (float*)whq32,
                                                    HID * VOCAB / 4);
    k_embed_mma<<<dim3(HID / 128, M_TOTAL / 128), 256, K1_SMEM>>>(X, We, Wxh, bh);
    k_rnn<<<NCTA, 256, RNN_SMEM>>>(Whh);
    // Round hidden states to tf32 (rne) for the output GEMM
    k_round<<<(M_TOTAL * HID / 4 + 255) / 256, 256>>>((const float*)hs,
                                                      (float*)hs32,
                                                      M_TOTAL * HID / 4);
    k_out_gemm2<<<dim3(M_TOTAL / BM3, VOCAB / BN3), 256, K3_SMEM>>>(bq, out);
}